// round 7
// baseline (speedup 1.0000x reference)
#include <cuda_runtime.h>
#include <cuda_fp16.h>
#include <cstdint>

// ---------------------------------------------------------------------------
// EdgeDecoder:
//   A'[n] = z[n] @ W1[0:128,:] + b1 ; B[n] = z[n] @ W1[128:256,:]
//   score[e] = relu(A'[src] + B[dst]) . W2 + b2
//
// Kernel 0 (prep, merged grid): blocks <64 convert W1 -> fp16 fused layout;
//   remaining blocks convert edge_index -> precomputed g_AB element offsets
//   (uint2{src*256, dst*256+128}) with dtype probe + clamp done once.
// Kernel 1 (gemm): persistent (grid=148), W fp16 smem-resident, z fp16 hi/lo
//   split, 2-term compensated HMMA (fp32 acc), stmatrix epilogue -> STG.128.
// Kernel 2 (edge): 8 lanes/edge, 4 edges/warp; lane owns 16 channels
//   (2x LDG.128 per half); W2 in regs; half2 add/relu, fp32 dot;
//   3-shfl reduce covers 4 edges at once.
// ---------------------------------------------------------------------------

#define HID 128
#define N_MAX 100000
#define E_MAX 1600000

__device__ __align__(16) __half g_AB[(size_t)N_MAX * 256];
__device__ __align__(16) __half g_Whi[128 * 256];
__device__ __align__(16) uint2  g_eidx[E_MAX];

// ---- tensor-core primitives ----
__device__ __forceinline__ void ldsm4(unsigned* r, const void* p) {
    unsigned a = (unsigned)__cvta_generic_to_shared(p);
    asm volatile("ldmatrix.sync.aligned.m8n8.x4.shared.b16 {%0,%1,%2,%3},[%4];"
                 : "=r"(r[0]), "=r"(r[1]), "=r"(r[2]), "=r"(r[3]) : "r"(a));
}
__device__ __forceinline__ void ldsm2t(unsigned* r, const void* p) {
    unsigned a = (unsigned)__cvta_generic_to_shared(p);
    asm volatile("ldmatrix.sync.aligned.m8n8.x2.trans.shared.b16 {%0,%1},[%2];"
                 : "=r"(r[0]), "=r"(r[1]) : "r"(a));
}
__device__ __forceinline__ void stsm4(void* p, unsigned r0, unsigned r1,
                                      unsigned r2, unsigned r3) {
    unsigned a = (unsigned)__cvta_generic_to_shared(p);
    asm volatile("stmatrix.sync.aligned.m8n8.x4.shared.b16 [%0],{%1,%2,%3,%4};"
                 :: "r"(a), "r"(r0), "r"(r1), "r"(r2), "r"(r3));
}
__device__ __forceinline__ void mma16816(float* c, const unsigned* a, const unsigned* b) {
    asm volatile(
        "mma.sync.aligned.m16n8k16.row.col.f32.f16.f16.f32 "
        "{%0,%1,%2,%3},{%4,%5,%6,%7},{%8,%9},{%0,%1,%2,%3};"
        : "+f"(c[0]), "+f"(c[1]), "+f"(c[2]), "+f"(c[3])
        : "r"(a[0]), "r"(a[1]), "r"(a[2]), "r"(a[3]), "r"(b[0]), "r"(b[1]));
}

// smem strides in halves; row byte strides 272/528 -> 16B shift/row, conflict-free
#define ZS 136
#define WS 264
#define OS 264
#define SMEM_BYTES ((128 * WS + 2 * 128 * ZS) * 2)   // 137,216 B

// ---------------------------------------------------------------------------
// Prep: blocks [0,64) -> W fp16; blocks [64, ...) -> edge offsets.
// ---------------------------------------------------------------------------
__global__ __launch_bounds__(512) void prep(
    const float* __restrict__ W1, const void* __restrict__ ei_raw,
    int E, int N)
{
    if (blockIdx.x < 64) {
        int idx = blockIdx.x * 512 + threadIdx.x;       // 0..32767
        int k = idx >> 8, j = idx & 255;
        float f = (j < 128) ? W1[(size_t)k * 128 + j]
                            : W1[(size_t)(128 + k) * 128 + (j - 128)];
        g_Whi[idx] = __float2half_rn(f);
        return;
    }

    // per-block dtype probe (L2-cached, 8 loads by one thread)
    __shared__ int is64s;
    if (threadIdx.x == 0) {
        const int* p = (const int*)ei_raw;
        int all0 = 1;
#pragma unroll
        for (int i = 0; i < 8; ++i) all0 &= (p[2 * i + 1] == 0);
        is64s = all0;
    }
    __syncthreads();

    int e = (blockIdx.x - 64) * 512 + threadIdx.x;
    if (e < E) {
        const int* p = (const int*)ei_raw;
        unsigned s, d;
        if (is64s) {                  // int64 LE: low word at 2*pos
            s = (unsigned)p[2 * (size_t)e];
            d = (unsigned)p[2 * ((size_t)E + e)];
        } else {
            s = (unsigned)p[e];
            d = (unsigned)p[(size_t)E + e];
        }
        s = min(s, (unsigned)(N - 1));
        d = min(d, (unsigned)(N - 1));
        g_eidx[e] = make_uint2(s * 256u, d * 256u + 128u);
    }
}

// ---------------------------------------------------------------------------
// Persistent GEMM, 2-term compensated.
// ---------------------------------------------------------------------------
__global__ __launch_bounds__(512, 1) void gemm_tc(
    const float* __restrict__ z,    // [N,128]
    const float* __restrict__ b1,   // [128]
    int N, int nstrips)
{
    extern __shared__ __align__(16) char dynsmem[];
    __half* Whi = (__half*)dynsmem;            // [128][WS]
    __half* Zhi = Whi + 128 * WS;              // [128][ZS]
    __half* Zlo = Zhi + 128 * ZS;
    __half* Stage = Zhi;                       // overlay [128][OS] over Zhi+Zlo

    const int t    = threadIdx.x;
    const int lane = t & 31;
    const int w    = t >> 5;

    // ---- load W fp16 into smem once (4096 uint4 over 512 threads) ----
#pragma unroll
    for (int i = 0; i < 8; ++i) {
        int idx = t + i * 512;
        int row = idx >> 5, c16 = idx & 31;
        *(uint4*)&Whi[row * WS + c16 * 8] = *(const uint4*)&g_Whi[row * 256 + c16 * 8];
    }
    __syncthreads();

    const int wm = w >> 3, wn = w & 7;
    const int mbase = wm * 64, nbase = wn * 32;
    const int arow = lane & 15, acol8 = (lane >> 4) << 3;
    const int brow = lane & 15;

    float bx[4], by[4];
#pragma unroll
    for (int nt = 0; nt < 4; ++nt) {
        int col = nbase + nt * 8 + (lane & 3) * 2;
        bx[nt] = (wn < 4) ? __ldg(b1 + col)     : 0.f;
        by[nt] = (wn < 4) ? __ldg(b1 + col + 1) : 0.f;
    }

    for (int strip = blockIdx.x; strip < nstrips; strip += gridDim.x) {
        const int row0 = strip * 128;

        // ---- Z fill: fp32 -> fp16 hi/lo ----
#pragma unroll
        for (int i = 0; i < 8; ++i) {
            int idx4 = t + i * 512;
            int r = idx4 >> 5, c = (idx4 & 31) * 4;
            int gr = row0 + r; if (gr >= N) gr = N - 1;
            float4 v = *(const float4*)(z + (size_t)gr * HID + c);
            __half2 h0 = __floats2half2_rn(v.x, v.y);
            __half2 h1 = __floats2half2_rn(v.z, v.w);
            float2 f0 = __half22float2(h0), f1 = __half22float2(h1);
            __half2 l0 = __floats2half2_rn(v.x - f0.x, v.y - f0.y);
            __half2 l1 = __floats2half2_rn(v.z - f1.x, v.w - f1.y);
            uint2 sh, sl;
            sh.x = *(unsigned*)&h0; sh.y = *(unsigned*)&h1;
            sl.x = *(unsigned*)&l0; sl.y = *(unsigned*)&l1;
            *(uint2*)&Zhi[r * ZS + c] = sh;
            *(uint2*)&Zlo[r * ZS + c] = sl;
        }
        __syncthreads();

        // ---- compute: Ah*Bh + Al*Bh, fp32 acc ----
        float acc[4][4][4];
#pragma unroll
        for (int mt = 0; mt < 4; ++mt)
#pragma unroll
            for (int nt = 0; nt < 4; ++nt)
#pragma unroll
                for (int q = 0; q < 4; ++q) acc[mt][nt][q] = 0.f;

#pragma unroll
        for (int ks = 0; ks < 8; ++ks) {
            const int k0 = ks * 16;
            unsigned ah[4][4], al[4][4];
#pragma unroll
            for (int mt = 0; mt < 4; ++mt) {
                const int rr = (mbase + mt * 16 + arow) * ZS + k0 + acol8;
                ldsm4(ah[mt], Zhi + rr);
                ldsm4(al[mt], Zlo + rr);
            }
#pragma unroll
            for (int nt = 0; nt < 4; ++nt) {
                unsigned bb[2];
                const int wr = (k0 + brow) * WS + nbase + nt * 8;
                ldsm2t(bb, Whi + wr);
#pragma unroll
                for (int mt = 0; mt < 4; ++mt) {
                    mma16816(acc[mt][nt], ah[mt], bb);
                    mma16816(acc[mt][nt], al[mt], bb);
                }
            }
        }
        __syncthreads();

        // ---- stmatrix epilogue into Stage ----
        const int stile = lane >> 3;
        const int srow  = lane & 7;
#pragma unroll
        for (int mt = 0; mt < 4; ++mt) {
            __half2 u[4], l[4];
#pragma unroll
            for (int nt = 0; nt < 4; ++nt) {
                u[nt] = __floats2half2_rn(acc[mt][nt][0] + bx[nt], acc[mt][nt][1] + by[nt]);
                l[nt] = __floats2half2_rn(acc[mt][nt][2] + bx[nt], acc[mt][nt][3] + by[nt]);
            }
            __half* pu = Stage + (mbase + mt * 16 + srow) * OS + nbase + stile * 8;
            __half* pl = Stage + (mbase + mt * 16 + 8 + srow) * OS + nbase + stile * 8;
            stsm4(pu, *(unsigned*)&u[0], *(unsigned*)&u[1], *(unsigned*)&u[2], *(unsigned*)&u[3]);
            stsm4(pl, *(unsigned*)&l[0], *(unsigned*)&l[1], *(unsigned*)&l[2], *(unsigned*)&l[3]);
        }
        __syncthreads();

        // ---- coalesced copy Stage -> g_AB ----
#pragma unroll
        for (int i = 0; i < 8; ++i) {
            int idx = t + i * 512;
            int r = idx >> 5, c16 = idx & 31;
            int gr = row0 + r;
            if (gr < N) {
                uint4 v = *(const uint4*)&Stage[r * OS + c16 * 8];
                *(uint4*)&g_AB[(size_t)gr * 256 + c16 * 8] = v;
            }
        }
        __syncthreads();
    }
}

// ---------------------------------------------------------------------------
// Edge kernel: 8 lanes/edge, 4 edges/warp, EDGE_ITER iterations.
// Lane gl owns channels 16*gl..16*gl+15 (2x uint4 per half).
// ---------------------------------------------------------------------------
#define EDGE_ITER 4

__global__ __launch_bounds__(256) void edge_score(
    const float* __restrict__ W2,
    const float* __restrict__ b2,
    float* __restrict__ out,
    int E)
{
    const int lane = threadIdx.x & 31;
    const int gl   = lane & 7;
    const int grp  = lane >> 3;                 // 0..3
    const int warp = threadIdx.x >> 5;
    const int ebase = (blockIdx.x * 8 + warp) * (4 * EDGE_ITER) + grp;
    const int choff = gl * 16;

    float ww[16];
#pragma unroll
    for (int q = 0; q < 4; ++q) {
        float4 v = *(const float4*)(W2 + choff + q * 4);
        ww[q * 4] = v.x; ww[q * 4 + 1] = v.y; ww[q * 4 + 2] = v.z; ww[q * 4 + 3] = v.w;
    }
    const float bias2 = __ldg(b2);
    const __half2 zero2 = __float2half2_rn(0.f);

#pragma unroll
    for (int it = 0; it < EDGE_ITER; ++it) {
        const int e = ebase + it * 4;
        float sum = 0.f;
        if (e < E) {
            const uint2 off = g_eidx[e];
            const uint4 a0 = *(const uint4*)(g_AB + off.x + choff);
            const uint4 a1 = *(const uint4*)(g_AB + off.x + choff + 8);
            const uint4 b0 = *(const uint4*)(g_AB + off.y + choff);
            const uint4 b1 = *(const uint4*)(g_AB + off.y + choff + 8);
            const unsigned* au0 = (const unsigned*)&a0;
            const unsigned* bu0 = (const unsigned*)&b0;
            const unsigned* au1 = (const unsigned*)&a1;
            const unsigned* bu1 = (const unsigned*)&b1;
#pragma unroll
            for (int i = 0; i < 4; ++i) {
                __half2 r = __hmax2(__hadd2(*(const __half2*)&au0[i],
                                            *(const __half2*)&bu0[i]), zero2);
                float2 f = __half22float2(r);
                sum = fmaf(f.x, ww[2 * i],     sum);
                sum = fmaf(f.y, ww[2 * i + 1], sum);
            }
#pragma unroll
            for (int i = 0; i < 4; ++i) {
                __half2 r = __hmax2(__hadd2(*(const __half2*)&au1[i],
                                            *(const __half2*)&bu1[i]), zero2);
                float2 f = __half22float2(r);
                sum = fmaf(f.x, ww[8 + 2 * i],     sum);
                sum = fmaf(f.y, ww[8 + 2 * i + 1], sum);
            }
        }
        // 8-lane group reduce (xor offsets 4,2,1 stay within aligned groups)
#pragma unroll
        for (int off8 = 4; off8; off8 >>= 1)
            sum += __shfl_xor_sync(0xFFFFFFFFu, sum, off8);

        if (gl == 0 && e < E)
            out[e] = sum + bias2;
    }
}

// ---------------------------------------------------------------------------
extern "C" void kernel_launch(void* const* d_in, const int* in_sizes, int n_in,
                              void* d_out, int out_size)
{
    const float* z   = (const float*)d_in[0];
    const void*  ei  = d_in[1];
    const float* W1  = (const float*)d_in[2];
    const float* b1  = (const float*)d_in[3];
    const float* W2  = (const float*)d_in[4];
    const float* b2  = (const float*)d_in[5];
    float*       out = (float*)d_out;

    const int N = in_sizes[0] / HID;   // 100000
    const int E = in_sizes[1] / 2;     // 1600000

    static int smem_set = 0;
    if (!smem_set) {
        cudaFuncSetAttribute(gemm_tc, cudaFuncAttributeMaxDynamicSharedMemorySize,
                             SMEM_BYTES);
        smem_set = 1;
    }

    prep<<<64 + (E + 511) / 512, 512>>>(W1, ei, E, N);

    const int nstrips = (N + 127) / 128;
    gemm_tc<<<148, 512, SMEM_BYTES>>>(z, b1, N, nstrips);

    const int edges_per_block = 8 * 4 * EDGE_ITER;   // 128
    edge_score<<<(E + edges_per_block - 1) / edges_per_block, 256>>>(
        W2, b2, out, E);
}

// round 8
// speedup vs baseline: 1.2807x; 1.2807x over previous
#include <cuda_runtime.h>
#include <cuda_fp16.h>
#include <cstdint>

// ---------------------------------------------------------------------------
// EdgeDecoder:
//   A'[n] = z[n] @ W1[0:128,:] + b1 ; B[n] = z[n] @ W1[128:256,:]
//   score[e] = relu(A'[src] + B[dst]) . W2 + b2
//
// Kernel 0 (prep): W1 -> fp16 fused [128][256] layout + dtype probe (R6).
// Kernel 1 (gemm): persistent, M-tile 64 rows -> smem 102.4KB -> 2 CTAs/SM
//   (R6 ran 1 CTA/SM at 137KB; barriers/fill latency now overlap across
//   co-resident blocks). 2-term compensated HMMA (Ah*Bh + Al*Bh, fp32 acc),
//   stmatrix epilogue -> coalesced STG.128.
// Kernel 2 (edge): R6 verbatim (16 lanes/edge, 2 edges/warp, 8 iters,
//   half2 add/relu, fp32 dot) — proven ~60us; R7's 8-lane variant regressed.
// ---------------------------------------------------------------------------

#define HID 128
#define N_MAX 100000

__device__ __align__(16) __half g_AB[(size_t)N_MAX * 256];
__device__ __align__(16) __half g_Whi[128 * 256];
__device__ int g_is64;

// ---- tensor-core primitives ----
__device__ __forceinline__ void ldsm4(unsigned* r, const void* p) {
    unsigned a = (unsigned)__cvta_generic_to_shared(p);
    asm volatile("ldmatrix.sync.aligned.m8n8.x4.shared.b16 {%0,%1,%2,%3},[%4];"
                 : "=r"(r[0]), "=r"(r[1]), "=r"(r[2]), "=r"(r[3]) : "r"(a));
}
__device__ __forceinline__ void ldsm2t(unsigned* r, const void* p) {
    unsigned a = (unsigned)__cvta_generic_to_shared(p);
    asm volatile("ldmatrix.sync.aligned.m8n8.x2.trans.shared.b16 {%0,%1},[%2];"
                 : "=r"(r[0]), "=r"(r[1]) : "r"(a));
}
__device__ __forceinline__ void stsm4(void* p, unsigned r0, unsigned r1,
                                      unsigned r2, unsigned r3) {
    unsigned a = (unsigned)__cvta_generic_to_shared(p);
    asm volatile("stmatrix.sync.aligned.m8n8.x4.shared.b16 [%0],{%1,%2,%3,%4};"
                 :: "r"(a), "r"(r0), "r"(r1), "r"(r2), "r"(r3));
}
__device__ __forceinline__ void mma16816(float* c, const unsigned* a, const unsigned* b) {
    asm volatile(
        "mma.sync.aligned.m16n8k16.row.col.f32.f16.f16.f32 "
        "{%0,%1,%2,%3},{%4,%5,%6,%7},{%8,%9},{%0,%1,%2,%3};"
        : "+f"(c[0]), "+f"(c[1]), "+f"(c[2]), "+f"(c[3])
        : "r"(a[0]), "r"(a[1]), "r"(a[2]), "r"(a[3]), "r"(b[0]), "r"(b[1]));
}

// smem strides in halves; row byte strides 272/528 -> 16B shift/row, conflict-free
#define ZS 136
#define WS 264
#define OS 264
#define MTILE 64
#define SMEM_BYTES ((128 * WS + 2 * MTILE * ZS) * 2)   // 102,400 B -> 2 CTAs/SM

// ---------------------------------------------------------------------------
// Prep (R6): fused-layout fp16 W + dtype probe.
// ---------------------------------------------------------------------------
__global__ __launch_bounds__(512) void prep_w(
    const float* __restrict__ W1, const int* __restrict__ ei32)
{
    if (blockIdx.x == 0 && threadIdx.x == 0) {
        int all0 = 1;
#pragma unroll
        for (int i = 0; i < 8; ++i) all0 &= (ei32[2 * i + 1] == 0);
        g_is64 = all0;
    }
    int idx = blockIdx.x * 512 + threadIdx.x;   // grid 64 -> 32768
    int k = idx >> 8, j = idx & 255;
    float f = (j < 128) ? W1[(size_t)k * 128 + j]
                        : W1[(size_t)(128 + k) * 128 + (j - 128)];
    g_Whi[idx] = __float2half_rn(f);
}

// ---------------------------------------------------------------------------
// Persistent GEMM, M-tile 64, 2 CTAs/SM, 2-term compensated.
// 16 warps = 2 (m) x 8 (n); warp tile 32 rows x 32 cols.
// ---------------------------------------------------------------------------
__global__ __launch_bounds__(512, 2) void gemm_tc(
    const float* __restrict__ z,    // [N,128]
    const float* __restrict__ b1,   // [128]
    int N, int nstrips)
{
    extern __shared__ __align__(16) char dynsmem[];
    __half* Whi = (__half*)dynsmem;            // [128][WS]
    __half* Zhi = Whi + 128 * WS;              // [MTILE][ZS]
    __half* Zlo = Zhi + MTILE * ZS;
    __half* Stage = Zhi;                       // overlay [MTILE][OS] over Zhi+Zlo
                                               // (33.8KB <= 34.8KB)

    const int t    = threadIdx.x;
    const int lane = t & 31;
    const int w    = t >> 5;

    // ---- load W fp16 into smem once (4096 uint4 over 512 threads) ----
#pragma unroll
    for (int i = 0; i < 8; ++i) {
        int idx = t + i * 512;
        int row = idx >> 5, c16 = idx & 31;
        *(uint4*)&Whi[row * WS + c16 * 8] = *(const uint4*)&g_Whi[row * 256 + c16 * 8];
    }
    __syncthreads();

    const int wm = w >> 3, wn = w & 7;         // 2 x 8
    const int mbase = wm * 32, nbase = wn * 32;
    const int arow = lane & 15, acol8 = (lane >> 4) << 3;
    const int brow = lane & 15;

    float bx[4], by[4];
#pragma unroll
    for (int nt = 0; nt < 4; ++nt) {
        int col = nbase + nt * 8 + (lane & 3) * 2;
        bx[nt] = (wn < 4) ? __ldg(b1 + col)     : 0.f;
        by[nt] = (wn < 4) ? __ldg(b1 + col + 1) : 0.f;
    }

    for (int strip = blockIdx.x; strip < nstrips; strip += gridDim.x) {
        const int row0 = strip * MTILE;

        // ---- Z fill: 64 rows x 128 = 2048 float4 over 512 thr -> 4 iters ----
#pragma unroll
        for (int i = 0; i < 4; ++i) {
            int idx4 = t + i * 512;
            int r = idx4 >> 5, c = (idx4 & 31) * 4;
            int gr = row0 + r; if (gr >= N) gr = N - 1;
            float4 v = *(const float4*)(z + (size_t)gr * HID + c);
            __half2 h0 = __floats2half2_rn(v.x, v.y);
            __half2 h1 = __floats2half2_rn(v.z, v.w);
            float2 f0 = __half22float2(h0), f1 = __half22float2(h1);
            __half2 l0 = __floats2half2_rn(v.x - f0.x, v.y - f0.y);
            __half2 l1 = __floats2half2_rn(v.z - f1.x, v.w - f1.y);
            uint2 sh, sl;
            sh.x = *(unsigned*)&h0; sh.y = *(unsigned*)&h1;
            sl.x = *(unsigned*)&l0; sl.y = *(unsigned*)&l1;
            *(uint2*)&Zhi[r * ZS + c] = sh;
            *(uint2*)&Zlo[r * ZS + c] = sl;
        }
        __syncthreads();

        // ---- compute: Ah*Bh + Al*Bh, fp32 acc; warp tile 32x32 ----
        float acc[2][4][4];
#pragma unroll
        for (int mt = 0; mt < 2; ++mt)
#pragma unroll
            for (int nt = 0; nt < 4; ++nt)
#pragma unroll
                for (int q = 0; q < 4; ++q) acc[mt][nt][q] = 0.f;

#pragma unroll
        for (int ks = 0; ks < 8; ++ks) {
            const int k0 = ks * 16;
            unsigned ah[2][4], al[2][4];
#pragma unroll
            for (int mt = 0; mt < 2; ++mt) {
                const int rr = (mbase + mt * 16 + arow) * ZS + k0 + acol8;
                ldsm4(ah[mt], Zhi + rr);
                ldsm4(al[mt], Zlo + rr);
            }
#pragma unroll
            for (int nt = 0; nt < 4; ++nt) {
                unsigned bb[2];
                const int wr = (k0 + brow) * WS + nbase + nt * 8;
                ldsm2t(bb, Whi + wr);
#pragma unroll
                for (int mt = 0; mt < 2; ++mt) {
                    mma16816(acc[mt][nt], ah[mt], bb);
                    mma16816(acc[mt][nt], al[mt], bb);
                }
            }
        }
        __syncthreads();   // all warps done reading Z before Stage overwrite

        // ---- stmatrix epilogue into Stage ----
        const int stile = lane >> 3;
        const int srow  = lane & 7;
#pragma unroll
        for (int mt = 0; mt < 2; ++mt) {
            __half2 u[4], l[4];
#pragma unroll
            for (int nt = 0; nt < 4; ++nt) {
                u[nt] = __floats2half2_rn(acc[mt][nt][0] + bx[nt], acc[mt][nt][1] + by[nt]);
                l[nt] = __floats2half2_rn(acc[mt][nt][2] + bx[nt], acc[mt][nt][3] + by[nt]);
            }
            __half* pu = Stage + (mbase + mt * 16 + srow) * OS + nbase + stile * 8;
            __half* pl = Stage + (mbase + mt * 16 + 8 + srow) * OS + nbase + stile * 8;
            stsm4(pu, *(unsigned*)&u[0], *(unsigned*)&u[1], *(unsigned*)&u[2], *(unsigned*)&u[3]);
            stsm4(pl, *(unsigned*)&l[0], *(unsigned*)&l[1], *(unsigned*)&l[2], *(unsigned*)&l[3]);
        }
        __syncthreads();

        // ---- coalesced copy Stage -> g_AB (64 rows x 32 uint4 = 2048) ----
#pragma unroll
        for (int i = 0; i < 4; ++i) {
            int idx = t + i * 512;
            int r = idx >> 5, c16 = idx & 31;
            int gr = row0 + r;
            if (gr < N) {
                uint4 v = *(const uint4*)&Stage[r * OS + c16 * 8];
                *(uint4*)&g_AB[(size_t)gr * 256 + c16 * 8] = v;
            }
        }
        __syncthreads();
    }
}

// ---------------------------------------------------------------------------
// Edge kernel (R6 verbatim): 16 lanes/edge, 2 edges/warp, 8 iters;
// half2 add/relu, fp32 dot.
// ---------------------------------------------------------------------------
#define EDGE_ITER 8

__global__ __launch_bounds__(256) void edge_score(
    const void* __restrict__ ei_raw,
    const float* __restrict__ W2,
    const float* __restrict__ b2,
    float* __restrict__ out,
    int E, int N)
{
    const int lane = threadIdx.x & 31;
    const int gl   = lane & 15;
    const int warp = threadIdx.x >> 5;
    const int ebase = (blockIdx.x * 8 + warp) * (2 * EDGE_ITER) + (lane >> 4);

    const float4 wwl = *(const float4*)(W2 + gl * 8);
    const float4 wwh = *(const float4*)(W2 + gl * 8 + 4);
    const float wwf[8] = {wwl.x, wwl.y, wwl.z, wwl.w, wwh.x, wwh.y, wwh.z, wwh.w};
    const float bias2 = __ldg(b2);
    const int is64 = g_is64;
    const __half2 zero2 = __float2half2_rn(0.f);

#pragma unroll
    for (int it = 0; it < EDGE_ITER; ++it) {
        const int e = ebase + it * 2;
        if (e >= E) return;

        unsigned s, d;
        if (is64) {
            const long long* ei = (const long long*)ei_raw;
            s = (unsigned)ei[e];
            d = (unsigned)ei[(size_t)E + e];
        } else {
            const int* ei = (const int*)ei_raw;
            s = (unsigned)ei[e];
            d = (unsigned)ei[(size_t)E + e];
        }
        s = min(s, (unsigned)(N - 1));
        d = min(d, (unsigned)(N - 1));

        const uint4 ar = *(const uint4*)(g_AB + (size_t)s * 256 + gl * 8);
        const uint4 br = *(const uint4*)(g_AB + (size_t)d * 256 + 128 + gl * 8);
        const unsigned* au = (const unsigned*)&ar;
        const unsigned* bu = (const unsigned*)&br;

        float sum = 0.f;
#pragma unroll
        for (int i = 0; i < 4; ++i) {
            __half2 r = __hmax2(__hadd2(*(const __half2*)&au[i],
                                        *(const __half2*)&bu[i]), zero2);
            float2 f = __half22float2(r);
            sum = fmaf(f.x, wwf[2 * i],     sum);
            sum = fmaf(f.y, wwf[2 * i + 1], sum);
        }
#pragma unroll
        for (int off = 8; off; off >>= 1)
            sum += __shfl_xor_sync(0xFFFFFFFFu, sum, off);

        if (gl == 0)
            out[e] = sum + bias2;
    }
}

// ---------------------------------------------------------------------------
extern "C" void kernel_launch(void* const* d_in, const int* in_sizes, int n_in,
                              void* d_out, int out_size)
{
    const float* z   = (const float*)d_in[0];
    const void*  ei  = d_in[1];
    const float* W1  = (const float*)d_in[2];
    const float* b1  = (const float*)d_in[3];
    const float* W2  = (const float*)d_in[4];
    const float* b2  = (const float*)d_in[5];
    float*       out = (float*)d_out;

    const int N = in_sizes[0] / HID;   // 100000
    const int E = in_sizes[1] / 2;     // 1600000

    static int smem_set = 0;
    if (!smem_set) {
        cudaFuncSetAttribute(gemm_tc, cudaFuncAttributeMaxDynamicSharedMemorySize,
                             SMEM_BYTES);
        smem_set = 1;
    }

    prep_w<<<64, 512>>>(W1, (const int*)ei);

    const int nstrips = (N + MTILE - 1) / MTILE;       // 1563
    gemm_tc<<<296, 512, SMEM_BYTES>>>(z, b1, N, nstrips);

    const int edges_per_block = 8 * 2 * EDGE_ITER;     // 128
    edge_score<<<(E + edges_per_block - 1) / edges_per_block, 256>>>(
        ei, W2, b2, out, E, N);
}